// round 15
// baseline (speedup 1.0000x reference)
#include <cuda_runtime.h>
#include <cuda_fp16.h>
#include <math.h>
#include <stdint.h>

#define N_NODES 50000
#define D_FEAT  128
#define HIDDEN  256
#define CLASSES 40
#define MAX_E   800000
#define BKT_CAP 64

// ---------------------------------------------------------------------------
// Scratch (device globals; allocation is forbidden)
// ---------------------------------------------------------------------------
__device__ __half g_xh [N_NODES * D_FEAT];      // x in fp16
__device__ __half g_ah [N_NODES * D_FEAT];      // agg1 in fp16
__device__ __half g_w1 [HIDDEN * 256];          // [Wr1|Wl1] fp16
__device__ __half g_w2 [80 * 256];              // [Wr2;Wl2] fp16 (0-39 q, 40-79 p)
__device__ __half g_hh [N_NODES * HIDDEN];      // layer-1 activations fp16
__device__ __half g_ph [N_NODES * CLASSES];     // h @ Wl2^T fp16 (gathered)
__device__ float  g_q  [N_NODES * CLASSES];     // h @ Wr2^T (root term, fp32)
__device__ int    g_cnt[N_NODES];
__device__ int    g_bkt[N_NODES * BKT_CAP];

static __device__ __forceinline__ int clampi(int v, int lo, int hi) {
    return v < lo ? lo : (v > hi ? hi : v);
}

__device__ __forceinline__ uint32_t smem_u32(const void* p) {
    uint32_t a;
    asm("{ .reg .u64 t; cvta.to.shared.u64 t, %1; cvt.u32.u64 %0, t; }"
        : "=r"(a) : "l"(p));
    return a;
}
__device__ __forceinline__ void cp16(uint32_t dst, const void* src, int sz) {
    asm volatile("cp.async.cg.shared.global [%0], [%1], 16, %2;"
                 :: "r"(dst), "l"(src), "r"(sz));
}
__device__ __forceinline__ void ldmx4(uint32_t* r, uint32_t addr) {
    asm volatile("ldmatrix.sync.aligned.m8n8.x4.shared.b16 {%0,%1,%2,%3}, [%4];"
                 : "=r"(r[0]), "=r"(r[1]), "=r"(r[2]), "=r"(r[3]) : "r"(addr));
}
__device__ __forceinline__ void mma16816(float* c, const uint32_t* a, const uint32_t* b) {
    asm volatile(
        "mma.sync.aligned.m16n8k16.row.col.f32.f16.f16.f32 "
        "{%0,%1,%2,%3}, {%4,%5,%6,%7}, {%8,%9}, {%0,%1,%2,%3};"
        : "+f"(c[0]), "+f"(c[1]), "+f"(c[2]), "+f"(c[3])
        : "r"(a[0]), "r"(a[1]), "r"(a[2]), "r"(a[3]), "r"(b[0]), "r"(b[1]));
}

// fp32x4 -> fp16x4 single rounding (uint2)
__device__ __forceinline__ uint2 pack_h4(float4 v) {
    __half2 a = __floats2half2_rn(v.x, v.y);
    __half2 b = __floats2half2_rn(v.z, v.w);
    uint2 r;
    r.x = *(uint32_t*)&a;
    r.y = *(uint32_t*)&b;
    return r;
}

// ---------------------------------------------------------------------------
// Fused conversion: x -> g_xh, W1 -> g_w1, W2 -> g_w2, zero g_cnt
// ---------------------------------------------------------------------------
__global__ void cvt_all(const float* __restrict__ x,
                        const float* __restrict__ Wr1, const float* __restrict__ Wl1,
                        const float* __restrict__ Wr2, const float* __restrict__ Wl2) {
    int t = blockIdx.x * blockDim.x + threadIdx.x;
    if (t < N_NODES) g_cnt[t] = 0;
    if (t < N_NODES * D_FEAT / 4)
        ((uint2*)g_xh)[t] = pack_h4(((const float4*)x)[t]);
    if (t < HIDDEN * 256 / 4) {
        int n = t >> 6, k = (t & 63) * 4;
        float4 v = (k < 128) ? *(const float4*)(Wr1 + (size_t)n * 128 + k)
                             : *(const float4*)(Wl1 + (size_t)n * 128 + k - 128);
        ((uint2*)g_w1)[t] = pack_h4(v);
    }
    if (t < 80 * 256 / 4) {
        int n = t >> 6, k = (t & 63) * 4;
        const float* W = (n < 40) ? (Wr2 + (size_t)n * HIDDEN)
                                  : (Wl2 + (size_t)(n - 40) * HIDDEN);
        ((uint2*)g_w2)[t] = pack_h4(*(const float4*)(W + k));
    }
}

// ---------------------------------------------------------------------------
// Bucket fill: one atomic per edge, int4-vectorized edge reads
// ---------------------------------------------------------------------------
__global__ void fill_bkt(const int* __restrict__ src,
                         const int* __restrict__ dst, int E) {
    int t = blockIdx.x * blockDim.x + threadIdx.x;
    int E4 = E >> 2;
    if (t < E4) {
        int4 d4 = ((const int4*)dst)[t];
        int4 s4 = ((const int4*)src)[t];
        int d, c;
        d = clampi(d4.x, 0, N_NODES - 1); c = atomicAdd(&g_cnt[d], 1);
        if (c < BKT_CAP) g_bkt[d * BKT_CAP + c] = clampi(s4.x, 0, N_NODES - 1);
        d = clampi(d4.y, 0, N_NODES - 1); c = atomicAdd(&g_cnt[d], 1);
        if (c < BKT_CAP) g_bkt[d * BKT_CAP + c] = clampi(s4.y, 0, N_NODES - 1);
        d = clampi(d4.z, 0, N_NODES - 1); c = atomicAdd(&g_cnt[d], 1);
        if (c < BKT_CAP) g_bkt[d * BKT_CAP + c] = clampi(s4.z, 0, N_NODES - 1);
        d = clampi(d4.w, 0, N_NODES - 1); c = atomicAdd(&g_cnt[d], 1);
        if (c < BKT_CAP) g_bkt[d * BKT_CAP + c] = clampi(s4.w, 0, N_NODES - 1);
    } else if (t == E4) {
        for (int e = E4 * 4; e < E; e++) {
            int d = clampi(dst[e], 0, N_NODES - 1);
            int c = atomicAdd(&g_cnt[d], 1);
            if (c < BKT_CAP)
                g_bkt[d * BKT_CAP + c] = clampi(src[e], 0, N_NODES - 1);
        }
    }
}

// ---------------------------------------------------------------------------
// Gather-mean of x (fp16), HALF-WARP (16 lanes) per node -> g_ah (fp16).
// 8 edges per iteration, two depth-2 HADD2 trees, fp32 accumulate.
// ---------------------------------------------------------------------------
__global__ void agg_gather_x() {
    const uint4* __restrict__ feat = (const uint4*)g_xh;   // 16 uint4 per row
    int hw = (blockIdx.x * blockDim.x + threadIdx.x) >> 4;
    int l16 = threadIdx.x & 15;
    if (hw >= N_NODES) return;

    int cnt = clampi(g_cnt[hw], 0, BKT_CAP);
    const int* bkt = g_bkt + hw * BKT_CAP;

    float2 acc[4];
#pragma unroll
    for (int j = 0; j < 4; j++) acc[j] = make_float2(0.f, 0.f);

    int i = 0;
    for (; i + 7 < cnt; i += 8) {
        int4 sa = *(const int4*)&bkt[i];
        int4 sb = *(const int4*)&bkt[i + 4];
        uint4 u0 = feat[sa.x * 16 + l16];
        uint4 u1 = feat[sa.y * 16 + l16];
        uint4 u2 = feat[sa.z * 16 + l16];
        uint4 u3 = feat[sa.w * 16 + l16];
        uint4 u4 = feat[sb.x * 16 + l16];
        uint4 u5 = feat[sb.y * 16 + l16];
        uint4 u6 = feat[sb.z * 16 + l16];
        uint4 u7 = feat[sb.w * 16 + l16];
        const uint32_t* p0 = &u0.x; const uint32_t* p1 = &u1.x;
        const uint32_t* p2 = &u2.x; const uint32_t* p3 = &u3.x;
        const uint32_t* p4 = &u4.x; const uint32_t* p5 = &u5.x;
        const uint32_t* p6 = &u6.x; const uint32_t* p7 = &u7.x;
#pragma unroll
        for (int j = 0; j < 4; j++) {
            __half2 a01 = __hadd2(*(__half2*)&p0[j], *(__half2*)&p1[j]);
            __half2 a23 = __hadd2(*(__half2*)&p2[j], *(__half2*)&p3[j]);
            float2 fA = __half22float2(__hadd2(a01, a23));
            __half2 b01 = __hadd2(*(__half2*)&p4[j], *(__half2*)&p5[j]);
            __half2 b23 = __hadd2(*(__half2*)&p6[j], *(__half2*)&p7[j]);
            float2 fB = __half22float2(__hadd2(b01, b23));
            acc[j].x += fA.x + fB.x;
            acc[j].y += fA.y + fB.y;
        }
    }
    if (i + 3 < cnt) {
        int4 s = *(const int4*)&bkt[i];
        uint4 u0 = feat[s.x * 16 + l16];
        uint4 u1 = feat[s.y * 16 + l16];
        uint4 u2 = feat[s.z * 16 + l16];
        uint4 u3 = feat[s.w * 16 + l16];
        const uint32_t* p0 = &u0.x; const uint32_t* p1 = &u1.x;
        const uint32_t* p2 = &u2.x; const uint32_t* p3 = &u3.x;
#pragma unroll
        for (int j = 0; j < 4; j++) {
            __half2 s01 = __hadd2(*(__half2*)&p0[j], *(__half2*)&p1[j]);
            __half2 s23 = __hadd2(*(__half2*)&p2[j], *(__half2*)&p3[j]);
            float2 f = __half22float2(__hadd2(s01, s23));
            acc[j].x += f.x; acc[j].y += f.y;
        }
        i += 4;
    }
    if (i + 1 < cnt) {
        int i0 = bkt[i], i1 = bkt[i + 1];
        uint4 u0 = feat[i0 * 16 + l16];
        uint4 u1 = feat[i1 * 16 + l16];
        const uint32_t* p0 = &u0.x; const uint32_t* p1 = &u1.x;
#pragma unroll
        for (int j = 0; j < 4; j++) {
            float2 f = __half22float2(__hadd2(*(__half2*)&p0[j], *(__half2*)&p1[j]));
            acc[j].x += f.x; acc[j].y += f.y;
        }
        i += 2;
    }
    if (i < cnt) {
        uint4 u0 = feat[bkt[i] * 16 + l16];
        const uint32_t* p0 = &u0.x;
#pragma unroll
        for (int j = 0; j < 4; j++) {
            float2 f = __half22float2(*(__half2*)&p0[j]);
            acc[j].x += f.x; acc[j].y += f.y;
        }
    }

    float inv = 1.0f / (float)(cnt > 0 ? cnt : 1);
    uint4 o;
    uint32_t* po = &o.x;
#pragma unroll
    for (int j = 0; j < 4; j++) {
        __half2 h = __floats2half2_rn(acc[j].x * inv, acc[j].y * inv);
        po[j] = *(uint32_t*)&h;
    }
    ((uint4*)g_ah)[hw * 16 + l16] = o;
}

// ---------------------------------------------------------------------------
// GEMM1: h = relu([x|agg] @ [Wr1;Wl1]^T + bl1) -> g_hh (fp16)
// HMMA fp16 single-pass. BM=128, BN=128, 512 threads (16 warps, 4x4 grid,
// warp tile 32x32). K=4x64 double-buffered. 2 CTAs/SM -> 32 warps/SM.
// ---------------------------------------------------------------------------
#define PITCHB 144                        // bytes per smem row (64 fp16 + pad)
#define G1_A   (128 * PITCHB)             // 18432
#define G1_B   (128 * PITCHB)             // 18432
#define G1_STG (G1_A + G1_B)              // 36864
#define G1_SM  (2 * G1_STG)               // 73728

__global__ __launch_bounds__(512, 2)
void gemm1_mma(const float* __restrict__ bl1) {
    extern __shared__ char sm[];
    const uint32_t smb = smem_u32(sm);
    const int tid = threadIdx.x;
    const int lane = tid & 31, wid = tid >> 5;
    const int mwarp = wid & 3, nwarp = wid >> 2;   // 4 x 4
    const int group = lane >> 2, tig = lane & 3;
    const int bm = blockIdx.x * 128;
    const int bnG = blockIdx.y * 128;

    float acc[2][4][4];
#pragma unroll
    for (int mt = 0; mt < 2; mt++)
#pragma unroll
        for (int nt = 0; nt < 4; nt++)
#pragma unroll
            for (int j = 0; j < 4; j++) acc[mt][nt][j] = 0.f;

    const int aRow = lane & 15;
    const int aColB = (lane >> 4) * 16;
    const int bRow = (lane & 7) + ((lane & 16) ? 8 : 0);
    const int bColB = ((lane >> 3) & 1) * 16;

    auto load_chunk = [&](int kc, int stage) {
        const __half* A = (kc < 2) ? g_xh : g_ah;
        const int koffA = (kc & 1) * 64;
        const int koffW = kc * 64;
        const uint32_t base = smb + stage * G1_STG;
#pragma unroll
        for (int i = tid; i < 1024; i += 512) {
            int r = i >> 3, c = i & 7;
            uint32_t so = (uint32_t)(r * PITCHB + c * 16);
            int gr = bm + r;
            int sz = (gr < N_NODES) ? 16 : 0;
            int grc = clampi(gr, 0, N_NODES - 1);
            cp16(base + so, A + (size_t)grc * 128 + koffA + c * 8, sz);
            cp16(base + G1_A + so,
                 g_w1 + (size_t)(bnG + r) * 256 + koffW + c * 8, 16);
        }
        asm volatile("cp.async.commit_group;" ::: "memory");
    };

    load_chunk(0, 0);

    for (int kc = 0; kc < 4; kc++) {
        if (kc < 3) {
            load_chunk(kc + 1, (kc + 1) & 1);
            asm volatile("cp.async.wait_group 1;" ::: "memory");
        } else {
            asm volatile("cp.async.wait_group 0;" ::: "memory");
        }
        __syncthreads();

        const uint32_t base = smb + (kc & 1) * G1_STG;
        const uint32_t sA = base, sB = base + G1_A;

#pragma unroll
        for (int k16 = 0; k16 < 4; k16++) {
            const int kbB = k16 * 32;
            uint32_t a[2][4], bh[4][2];
#pragma unroll
            for (int mt = 0; mt < 2; mt++) {
                uint32_t ad = (uint32_t)((mwarp * 32 + mt * 16 + aRow) * PITCHB
                                         + kbB + aColB);
                ldmx4(a[mt], sA + ad);
            }
#pragma unroll
            for (int np = 0; np < 2; np++) {
                uint32_t bd = (uint32_t)((nwarp * 32 + np * 16 + bRow) * PITCHB
                                         + kbB + bColB);
                uint32_t th[4];
                ldmx4(th, sB + bd);
                bh[np * 2][0] = th[0]; bh[np * 2][1] = th[1];
                bh[np * 2 + 1][0] = th[2]; bh[np * 2 + 1][1] = th[3];
            }
#pragma unroll
            for (int mt = 0; mt < 2; mt++)
#pragma unroll
                for (int nt = 0; nt < 4; nt++)
                    mma16816(acc[mt][nt], a[mt], bh[nt]);
        }
        __syncthreads();
    }

    // Epilogue: bias + ReLU -> g_hh (fp16)
#pragma unroll
    for (int mt = 0; mt < 2; mt++) {
        int row0 = bm + mwarp * 32 + mt * 16 + group;
        int row1 = row0 + 8;
#pragma unroll
        for (int nt = 0; nt < 4; nt++) {
            int col = bnG + nwarp * 32 + nt * 8 + tig * 2;
            float b0 = __ldg(&bl1[col]), b1 = __ldg(&bl1[col + 1]);
            if (row0 < N_NODES) {
                __half2 o = __floats2half2_rn(fmaxf(acc[mt][nt][0] + b0, 0.f),
                                              fmaxf(acc[mt][nt][1] + b1, 0.f));
                *(uint32_t*)(g_hh + (size_t)row0 * HIDDEN + col) = *(uint32_t*)&o;
            }
            if (row1 < N_NODES) {
                __half2 o = __floats2half2_rn(fmaxf(acc[mt][nt][2] + b0, 0.f),
                                              fmaxf(acc[mt][nt][3] + b1, 0.f));
                *(uint32_t*)(g_hh + (size_t)row1 * HIDDEN + col) = *(uint32_t*)&o;
            }
        }
    }
}

// ---------------------------------------------------------------------------
// GEMM2: [q|p] = h @ [Wr2;Wl2]^T  (HMMA fp16 single-pass)
// q -> fp32 g_q, p -> fp16 g_ph.
// ---------------------------------------------------------------------------
#define G2_A   (128 * PITCHB)             // 18432
#define G2_B   (80 * PITCHB)              // 11520
#define G2_STG (G2_A + G2_B)              // 29952
#define G2_SM  (2 * G2_STG)               // 59904

__global__ __launch_bounds__(256, 2)
void gemm2_mma() {
    extern __shared__ char sm[];
    const uint32_t smb = smem_u32(sm);
    const int tid = threadIdx.x;
    const int lane = tid & 31, wid = tid >> 5;
    const int group = lane >> 2, tig = lane & 3;
    const int bm = blockIdx.x * 128;

    float acc[10][4];
#pragma unroll
    for (int nt = 0; nt < 10; nt++)
#pragma unroll
        for (int j = 0; j < 4; j++) acc[nt][j] = 0.f;

    const int aRow = lane & 15;
    const int aColB = (lane >> 4) * 16;
    const int bRow = (lane & 7) + ((lane & 16) ? 8 : 0);
    const int bColB = ((lane >> 3) & 1) * 16;

    auto load_chunk = [&](int kc, int stage) {
        const int koff = kc * 64;
        const uint32_t base = smb + stage * G2_STG;
#pragma unroll
        for (int i = tid; i < 1024; i += 256) {
            int r = i >> 3, c = i & 7;
            int gr = bm + r;
            int sz = (gr < N_NODES) ? 16 : 0;
            int grc = clampi(gr, 0, N_NODES - 1);
            cp16(base + (uint32_t)(r * PITCHB + c * 16),
                 g_hh + (size_t)grc * HIDDEN + koff + c * 8, sz);
        }
#pragma unroll
        for (int i = tid; i < 640; i += 256) {
            int r = i >> 3, c = i & 7;
            cp16(base + G2_A + (uint32_t)(r * PITCHB + c * 16),
                 g_w2 + (size_t)r * 256 + koff + c * 8, 16);
        }
        asm volatile("cp.async.commit_group;" ::: "memory");
    };

    load_chunk(0, 0);

    for (int kc = 0; kc < 4; kc++) {
        if (kc < 3) {
            load_chunk(kc + 1, (kc + 1) & 1);
            asm volatile("cp.async.wait_group 1;" ::: "memory");
        } else {
            asm volatile("cp.async.wait_group 0;" ::: "memory");
        }
        __syncthreads();

        const uint32_t base = smb + (kc & 1) * G2_STG;
        const uint32_t sA = base, sB = base + G2_A;

#pragma unroll
        for (int k16 = 0; k16 < 4; k16++) {
            const int kbB = k16 * 32;
            uint32_t a[4], bh[10][2];
            {
                uint32_t ad = (uint32_t)((wid * 16 + aRow) * PITCHB + kbB + aColB);
                ldmx4(a, sA + ad);
            }
#pragma unroll
            for (int np = 0; np < 5; np++) {
                uint32_t bd = (uint32_t)((np * 16 + bRow) * PITCHB + kbB + bColB);
                uint32_t th[4];
                ldmx4(th, sB + bd);
                bh[np * 2][0] = th[0]; bh[np * 2][1] = th[1];
                bh[np * 2 + 1][0] = th[2]; bh[np * 2 + 1][1] = th[3];
            }
#pragma unroll
            for (int nt = 0; nt < 10; nt++)
                mma16816(acc[nt], a, bh[nt]);
        }
        __syncthreads();
    }

    // Epilogue: cols 0-39 -> g_q (fp32), cols 40-79 -> g_ph (fp16)
    int row0 = bm + wid * 16 + group;
    int row1 = row0 + 8;
#pragma unroll
    for (int nt = 0; nt < 10; nt++) {
        int col = nt * 8 + tig * 2;
        if (col < 40) {
            if (row0 < N_NODES)
                *(float2*)(g_q + (size_t)row0 * CLASSES + col) =
                    make_float2(acc[nt][0], acc[nt][1]);
            if (row1 < N_NODES)
                *(float2*)(g_q + (size_t)row1 * CLASSES + col) =
                    make_float2(acc[nt][2], acc[nt][3]);
        } else {
            int c = col - 40;
            if (row0 < N_NODES) {
                __half2 o = __floats2half2_rn(acc[nt][0], acc[nt][1]);
                *(uint32_t*)(g_ph + (size_t)row0 * CLASSES + c) = *(uint32_t*)&o;
            }
            if (row1 < N_NODES) {
                __half2 o = __floats2half2_rn(acc[nt][2], acc[nt][3]);
                *(uint32_t*)(g_ph + (size_t)row1 * CLASSES + c) = *(uint32_t*)&o;
            }
        }
    }
}

// ---------------------------------------------------------------------------
// Final fused: out[i] = log_softmax( q[i] + mean_{s in N(i)} p[s] + bl2 )
// ---------------------------------------------------------------------------
__global__ void final_agg_softmax(const float* __restrict__ bl2,
                                  float* __restrict__ out) {
    int w = (blockIdx.x * blockDim.x + threadIdx.x) >> 5;
    int lane = threadIdx.x & 31;
    if (w >= N_NODES) return;

    const bool act = lane < CLASSES / 2;
    int cnt = clampi(g_cnt[w], 0, BKT_CAP);
    const int* bkt = g_bkt + w * BKT_CAP;

    float ax = 0.f, ay = 0.f;
    int i = 0;
    for (; i + 3 < cnt; i += 4) {
        int4 s = *(const int4*)&bkt[i];
        if (act) {
            uint32_t u0 = *(const uint32_t*)&g_ph[s.x * CLASSES + 2 * lane];
            uint32_t u1 = *(const uint32_t*)&g_ph[s.y * CLASSES + 2 * lane];
            uint32_t u2 = *(const uint32_t*)&g_ph[s.z * CLASSES + 2 * lane];
            uint32_t u3 = *(const uint32_t*)&g_ph[s.w * CLASSES + 2 * lane];
            __half2 s01 = __hadd2(*(__half2*)&u0, *(__half2*)&u1);
            __half2 s23 = __hadd2(*(__half2*)&u2, *(__half2*)&u3);
            float2 v = __half22float2(__hadd2(s01, s23));
            ax += v.x; ay += v.y;
        }
    }
    for (; i < cnt; i++) {
        int s0 = bkt[i];
        if (act) {
            uint32_t u0 = *(const uint32_t*)&g_ph[s0 * CLASSES + 2 * lane];
            float2 v = __half22float2(*(__half2*)&u0);
            ax += v.x; ay += v.y;
        }
    }
    float inv = 1.0f / (float)(cnt > 0 ? cnt : 1);

    float vx = -INFINITY, vy = -INFINITY;
    if (act) {
        float2 q = *(const float2*)&g_q[(size_t)w * CLASSES + 2 * lane];
        float2 b = *(const float2*)&bl2[2 * lane];
        vx = q.x + b.x + ax * inv;
        vy = q.y + b.y + ay * inv;
    }

    float mx = fmaxf(vx, vy);
#pragma unroll
    for (int o = 16; o; o >>= 1) mx = fmaxf(mx, __shfl_xor_sync(0xffffffffu, mx, o));
    float s = act ? (expf(vx - mx) + expf(vy - mx)) : 0.f;
#pragma unroll
    for (int o = 16; o; o >>= 1) s += __shfl_xor_sync(0xffffffffu, s, o);
    float l = mx + logf(s);

    if (act) {
        float2 r; r.x = vx - l; r.y = vy - l;
        *(float2*)&out[(size_t)w * CLASSES + 2 * lane] = r;
    }
}

// ---------------------------------------------------------------------------
// Host launcher (graph-capturable: kernel launches only)
// ---------------------------------------------------------------------------
extern "C" void kernel_launch(void* const* d_in, const int* in_sizes, int n_in,
                              void* d_out, int out_size) {
    const float* x   = (const float*)d_in[0];
    const int*   ei  = (const int*)d_in[1];      // int32 (JAX x64 disabled)
    const float* Wl1 = (const float*)d_in[2];
    const float* bl1 = (const float*)d_in[3];
    const float* Wr1 = (const float*)d_in[4];
    const float* Wl2 = (const float*)d_in[5];
    const float* bl2 = (const float*)d_in[6];
    const float* Wr2 = (const float*)d_in[7];
    float*       out = (float*)d_out;

    const int E = in_sizes[1] / 2;
    const int* src = ei;
    const int* dst = ei + E;

    cudaFuncSetAttribute(gemm1_mma, cudaFuncAttributeMaxDynamicSharedMemorySize, G1_SM);
    cudaFuncSetAttribute(gemm2_mma, cudaFuncAttributeMaxDynamicSharedMemorySize, G2_SM);

    // 1. fused conversion (x, W1, W2) + zero counters
    cvt_all<<<(N_NODES * D_FEAT / 4 + 255) / 256, 256>>>(x, Wr1, Wl1, Wr2, Wl2);

    // 2. bucket fill (CSR replacement), 4 edges per thread
    fill_bkt<<<(E / 4 + 256) / 256, 256>>>(src, dst, E);

    // 3. aggregate x (fp16 source), half-warp per node, 8-deep pipeline
    agg_gather_x<<<(N_NODES * 16 + 255) / 256, 256>>>();

    // 4. layer 1 (HMMA fp16, BM=128 BN=128, 512 threads, 32 warps/SM)
    {
        dim3 grid((N_NODES + 127) / 128, HIDDEN / 128);
        gemm1_mma<<<grid, 512, G1_SM>>>(bl1);
    }

    // 5. layer 2 projections (merged q|p)
    gemm2_mma<<<(N_NODES + 127) / 128, 256, G2_SM>>>();

    // 6. fused mean-aggregate(p fp16) + q + bias + log_softmax
    final_agg_softmax<<<(N_NODES * 32 + 255) / 256, 256>>>(bl2, out);
}

// round 16
// speedup vs baseline: 1.0429x; 1.0429x over previous
#include <cuda_runtime.h>
#include <cuda_fp16.h>
#include <math.h>
#include <stdint.h>

#define N_NODES 50000
#define D_FEAT  128
#define HIDDEN  256
#define CLASSES 40
#define MAX_E   800000
#define BKT_CAP 64

// ---------------------------------------------------------------------------
// Scratch (device globals; allocation is forbidden)
// ---------------------------------------------------------------------------
__device__ __half g_xh [N_NODES * D_FEAT];      // x in fp16
__device__ __half g_ah [N_NODES * D_FEAT];      // agg1 in fp16
__device__ __half g_w1 [HIDDEN * 256];          // [Wr1|Wl1] fp16
__device__ __half g_w2 [80 * 256];              // [Wr2;Wl2] fp16 (0-39 q, 40-79 p)
__device__ __half g_hh [N_NODES * HIDDEN];      // layer-1 activations fp16
__device__ __half g_ph [N_NODES * CLASSES];     // h @ Wl2^T fp16 (gathered)
__device__ float  g_q  [N_NODES * CLASSES];     // h @ Wr2^T (root term, fp32)
__device__ int    g_cnt[N_NODES];
__device__ int    g_bkt[N_NODES * BKT_CAP];

static __device__ __forceinline__ int clampi(int v, int lo, int hi) {
    return v < lo ? lo : (v > hi ? hi : v);
}

__device__ __forceinline__ uint32_t smem_u32(const void* p) {
    uint32_t a;
    asm("{ .reg .u64 t; cvta.to.shared.u64 t, %1; cvt.u32.u64 %0, t; }"
        : "=r"(a) : "l"(p));
    return a;
}
__device__ __forceinline__ void cp16(uint32_t dst, const void* src, int sz) {
    asm volatile("cp.async.cg.shared.global [%0], [%1], 16, %2;"
                 :: "r"(dst), "l"(src), "r"(sz));
}
__device__ __forceinline__ void ldmx4(uint32_t* r, uint32_t addr) {
    asm volatile("ldmatrix.sync.aligned.m8n8.x4.shared.b16 {%0,%1,%2,%3}, [%4];"
                 : "=r"(r[0]), "=r"(r[1]), "=r"(r[2]), "=r"(r[3]) : "r"(addr));
}
__device__ __forceinline__ void mma16816(float* c, const uint32_t* a, const uint32_t* b) {
    asm volatile(
        "mma.sync.aligned.m16n8k16.row.col.f32.f16.f16.f32 "
        "{%0,%1,%2,%3}, {%4,%5,%6,%7}, {%8,%9}, {%0,%1,%2,%3};"
        : "+f"(c[0]), "+f"(c[1]), "+f"(c[2]), "+f"(c[3])
        : "r"(a[0]), "r"(a[1]), "r"(a[2]), "r"(a[3]), "r"(b[0]), "r"(b[1]));
}

// fp32x4 -> fp16x4 single rounding (uint2)
__device__ __forceinline__ uint2 pack_h4(float4 v) {
    __half2 a = __floats2half2_rn(v.x, v.y);
    __half2 b = __floats2half2_rn(v.z, v.w);
    uint2 r;
    r.x = *(uint32_t*)&a;
    r.y = *(uint32_t*)&b;
    return r;
}

// ---------------------------------------------------------------------------
// Fused conversion: x -> g_xh, W1 -> g_w1, W2 -> g_w2, zero g_cnt
// ---------------------------------------------------------------------------
__global__ void cvt_all(const float* __restrict__ x,
                        const float* __restrict__ Wr1, const float* __restrict__ Wl1,
                        const float* __restrict__ Wr2, const float* __restrict__ Wl2) {
    int t = blockIdx.x * blockDim.x + threadIdx.x;
    if (t < N_NODES) g_cnt[t] = 0;
    if (t < N_NODES * D_FEAT / 4)
        ((uint2*)g_xh)[t] = pack_h4(((const float4*)x)[t]);
    if (t < HIDDEN * 256 / 4) {
        int n = t >> 6, k = (t & 63) * 4;
        float4 v = (k < 128) ? *(const float4*)(Wr1 + (size_t)n * 128 + k)
                             : *(const float4*)(Wl1 + (size_t)n * 128 + k - 128);
        ((uint2*)g_w1)[t] = pack_h4(v);
    }
    if (t < 80 * 256 / 4) {
        int n = t >> 6, k = (t & 63) * 4;
        const float* W = (n < 40) ? (Wr2 + (size_t)n * HIDDEN)
                                  : (Wl2 + (size_t)(n - 40) * HIDDEN);
        ((uint2*)g_w2)[t] = pack_h4(*(const float4*)(W + k));
    }
}

// ---------------------------------------------------------------------------
// Bucket fill: one atomic per edge, int4-vectorized edge reads
// ---------------------------------------------------------------------------
__global__ void fill_bkt(const int* __restrict__ src,
                         const int* __restrict__ dst, int E) {
    int t = blockIdx.x * blockDim.x + threadIdx.x;
    int E4 = E >> 2;
    if (t < E4) {
        int4 d4 = ((const int4*)dst)[t];
        int4 s4 = ((const int4*)src)[t];
        int d, c;
        d = clampi(d4.x, 0, N_NODES - 1); c = atomicAdd(&g_cnt[d], 1);
        if (c < BKT_CAP) g_bkt[d * BKT_CAP + c] = clampi(s4.x, 0, N_NODES - 1);
        d = clampi(d4.y, 0, N_NODES - 1); c = atomicAdd(&g_cnt[d], 1);
        if (c < BKT_CAP) g_bkt[d * BKT_CAP + c] = clampi(s4.y, 0, N_NODES - 1);
        d = clampi(d4.z, 0, N_NODES - 1); c = atomicAdd(&g_cnt[d], 1);
        if (c < BKT_CAP) g_bkt[d * BKT_CAP + c] = clampi(s4.z, 0, N_NODES - 1);
        d = clampi(d4.w, 0, N_NODES - 1); c = atomicAdd(&g_cnt[d], 1);
        if (c < BKT_CAP) g_bkt[d * BKT_CAP + c] = clampi(s4.w, 0, N_NODES - 1);
    } else if (t == E4) {
        for (int e = E4 * 4; e < E; e++) {
            int d = clampi(dst[e], 0, N_NODES - 1);
            int c = atomicAdd(&g_cnt[d], 1);
            if (c < BKT_CAP)
                g_bkt[d * BKT_CAP + c] = clampi(src[e], 0, N_NODES - 1);
        }
    }
}

// ---------------------------------------------------------------------------
// Gather-mean of x (fp16), HALF-WARP (16 lanes) per node -> g_ah (fp16).
// 8 edges per iteration, two depth-2 HADD2 trees, fp32 accumulate.
// ---------------------------------------------------------------------------
__global__ void agg_gather_x() {
    const uint4* __restrict__ feat = (const uint4*)g_xh;   // 16 uint4 per row
    int hw = (blockIdx.x * blockDim.x + threadIdx.x) >> 4;
    int l16 = threadIdx.x & 15;
    if (hw >= N_NODES) return;

    int cnt = clampi(g_cnt[hw], 0, BKT_CAP);
    const int* bkt = g_bkt + hw * BKT_CAP;

    float2 acc[4];
#pragma unroll
    for (int j = 0; j < 4; j++) acc[j] = make_float2(0.f, 0.f);

    int i = 0;
    for (; i + 7 < cnt; i += 8) {
        int4 sa = *(const int4*)&bkt[i];
        int4 sb = *(const int4*)&bkt[i + 4];
        uint4 u0 = feat[sa.x * 16 + l16];
        uint4 u1 = feat[sa.y * 16 + l16];
        uint4 u2 = feat[sa.z * 16 + l16];
        uint4 u3 = feat[sa.w * 16 + l16];
        uint4 u4 = feat[sb.x * 16 + l16];
        uint4 u5 = feat[sb.y * 16 + l16];
        uint4 u6 = feat[sb.z * 16 + l16];
        uint4 u7 = feat[sb.w * 16 + l16];
        const uint32_t* p0 = &u0.x; const uint32_t* p1 = &u1.x;
        const uint32_t* p2 = &u2.x; const uint32_t* p3 = &u3.x;
        const uint32_t* p4 = &u4.x; const uint32_t* p5 = &u5.x;
        const uint32_t* p6 = &u6.x; const uint32_t* p7 = &u7.x;
#pragma unroll
        for (int j = 0; j < 4; j++) {
            __half2 a01 = __hadd2(*(__half2*)&p0[j], *(__half2*)&p1[j]);
            __half2 a23 = __hadd2(*(__half2*)&p2[j], *(__half2*)&p3[j]);
            float2 fA = __half22float2(__hadd2(a01, a23));
            __half2 b01 = __hadd2(*(__half2*)&p4[j], *(__half2*)&p5[j]);
            __half2 b23 = __hadd2(*(__half2*)&p6[j], *(__half2*)&p7[j]);
            float2 fB = __half22float2(__hadd2(b01, b23));
            acc[j].x += fA.x + fB.x;
            acc[j].y += fA.y + fB.y;
        }
    }
    if (i + 3 < cnt) {
        int4 s = *(const int4*)&bkt[i];
        uint4 u0 = feat[s.x * 16 + l16];
        uint4 u1 = feat[s.y * 16 + l16];
        uint4 u2 = feat[s.z * 16 + l16];
        uint4 u3 = feat[s.w * 16 + l16];
        const uint32_t* p0 = &u0.x; const uint32_t* p1 = &u1.x;
        const uint32_t* p2 = &u2.x; const uint32_t* p3 = &u3.x;
#pragma unroll
        for (int j = 0; j < 4; j++) {
            __half2 s01 = __hadd2(*(__half2*)&p0[j], *(__half2*)&p1[j]);
            __half2 s23 = __hadd2(*(__half2*)&p2[j], *(__half2*)&p3[j]);
            float2 f = __half22float2(__hadd2(s01, s23));
            acc[j].x += f.x; acc[j].y += f.y;
        }
        i += 4;
    }
    if (i + 1 < cnt) {
        int i0 = bkt[i], i1 = bkt[i + 1];
        uint4 u0 = feat[i0 * 16 + l16];
        uint4 u1 = feat[i1 * 16 + l16];
        const uint32_t* p0 = &u0.x; const uint32_t* p1 = &u1.x;
#pragma unroll
        for (int j = 0; j < 4; j++) {
            float2 f = __half22float2(__hadd2(*(__half2*)&p0[j], *(__half2*)&p1[j]));
            acc[j].x += f.x; acc[j].y += f.y;
        }
        i += 2;
    }
    if (i < cnt) {
        uint4 u0 = feat[bkt[i] * 16 + l16];
        const uint32_t* p0 = &u0.x;
#pragma unroll
        for (int j = 0; j < 4; j++) {
            float2 f = __half22float2(*(__half2*)&p0[j]);
            acc[j].x += f.x; acc[j].y += f.y;
        }
    }

    float inv = 1.0f / (float)(cnt > 0 ? cnt : 1);
    uint4 o;
    uint32_t* po = &o.x;
#pragma unroll
    for (int j = 0; j < 4; j++) {
        __half2 h = __floats2half2_rn(acc[j].x * inv, acc[j].y * inv);
        po[j] = *(uint32_t*)&h;
    }
    ((uint4*)g_ah)[hw * 16 + l16] = o;
}

// ---------------------------------------------------------------------------
// GEMM1: h = relu([x|agg] @ [Wr1;Wl1]^T + bl1) -> g_hh (fp16)
// HMMA fp16 single-pass. BM=128, BN=128, 256 thr (8 warps 4x2, 32x64 tile).
// K=4x64, THREE-stage pipeline, ONE sync per chunk.
// ---------------------------------------------------------------------------
#define PITCHB 144                        // bytes per smem row (64 fp16 + pad)
#define G1_A   (128 * PITCHB)             // 18432
#define G1_B   (128 * PITCHB)             // 18432
#define G1_STG (G1_A + G1_B)              // 36864
#define G1_SM  (3 * G1_STG)               // 110592

__global__ __launch_bounds__(256, 2)
void gemm1_mma(const float* __restrict__ bl1) {
    extern __shared__ char sm[];
    const uint32_t smb = smem_u32(sm);
    const int tid = threadIdx.x;
    const int lane = tid & 31, wid = tid >> 5;
    const int mwarp = wid & 3, nwarp = wid >> 2;   // 4 x 2
    const int group = lane >> 2, tig = lane & 3;
    const int bm = blockIdx.x * 128;
    const int bnG = blockIdx.y * 128;

    float acc[2][8][4];
#pragma unroll
    for (int mt = 0; mt < 2; mt++)
#pragma unroll
        for (int nt = 0; nt < 8; nt++)
#pragma unroll
            for (int j = 0; j < 4; j++) acc[mt][nt][j] = 0.f;

    const int aRow = lane & 15;
    const int aColB = (lane >> 4) * 16;
    const int bRow = (lane & 7) + ((lane & 16) ? 8 : 0);
    const int bColB = ((lane >> 3) & 1) * 16;

    auto load_chunk = [&](int kc, int stage) {
        const __half* A = (kc < 2) ? g_xh : g_ah;
        const int koffA = (kc & 1) * 64;
        const int koffW = kc * 64;
        const uint32_t base = smb + stage * G1_STG;
#pragma unroll
        for (int i = tid; i < 1024; i += 256) {
            int r = i >> 3, c = i & 7;
            uint32_t so = (uint32_t)(r * PITCHB + c * 16);
            int gr = bm + r;
            int sz = (gr < N_NODES) ? 16 : 0;
            int grc = clampi(gr, 0, N_NODES - 1);
            cp16(base + so, A + (size_t)grc * 128 + koffA + c * 8, sz);
            cp16(base + G1_A + so,
                 g_w1 + (size_t)(bnG + r) * 256 + koffW + c * 8, 16);
        }
        asm volatile("cp.async.commit_group;" ::: "memory");
    };

    load_chunk(0, 0);
    load_chunk(1, 1);

    for (int kc = 0; kc < 4; kc++) {
        if (kc < 3) {
            asm volatile("cp.async.wait_group 1;" ::: "memory");
        } else {
            asm volatile("cp.async.wait_group 0;" ::: "memory");
        }
        __syncthreads();                 // also fences compute on buf (kc+2)%3
        if (kc + 2 < 4) load_chunk(kc + 2, (kc + 2) % 3);

        const uint32_t base = smb + (kc % 3) * G1_STG;
        const uint32_t sA = base, sB = base + G1_A;

#pragma unroll
        for (int k16 = 0; k16 < 4; k16++) {
            const int kbB = k16 * 32;
            uint32_t a[2][4], bh[8][2];
#pragma unroll
            for (int mt = 0; mt < 2; mt++) {
                uint32_t ad = (uint32_t)((mwarp * 32 + mt * 16 + aRow) * PITCHB
                                         + kbB + aColB);
                ldmx4(a[mt], sA + ad);
            }
#pragma unroll
            for (int np = 0; np < 4; np++) {
                uint32_t bd = (uint32_t)((nwarp * 64 + np * 16 + bRow) * PITCHB
                                         + kbB + bColB);
                uint32_t th[4];
                ldmx4(th, sB + bd);
                bh[np * 2][0] = th[0]; bh[np * 2][1] = th[1];
                bh[np * 2 + 1][0] = th[2]; bh[np * 2 + 1][1] = th[3];
            }
#pragma unroll
            for (int mt = 0; mt < 2; mt++)
#pragma unroll
                for (int nt = 0; nt < 8; nt++)
                    mma16816(acc[mt][nt], a[mt], bh[nt]);
        }
    }

    // Epilogue: bias + ReLU -> g_hh (fp16)
#pragma unroll
    for (int mt = 0; mt < 2; mt++) {
        int row0 = bm + mwarp * 32 + mt * 16 + group;
        int row1 = row0 + 8;
#pragma unroll
        for (int nt = 0; nt < 8; nt++) {
            int col = bnG + nwarp * 64 + nt * 8 + tig * 2;
            float b0 = __ldg(&bl1[col]), b1 = __ldg(&bl1[col + 1]);
            if (row0 < N_NODES) {
                __half2 o = __floats2half2_rn(fmaxf(acc[mt][nt][0] + b0, 0.f),
                                              fmaxf(acc[mt][nt][1] + b1, 0.f));
                *(uint32_t*)(g_hh + (size_t)row0 * HIDDEN + col) = *(uint32_t*)&o;
            }
            if (row1 < N_NODES) {
                __half2 o = __floats2half2_rn(fmaxf(acc[mt][nt][2] + b0, 0.f),
                                              fmaxf(acc[mt][nt][3] + b1, 0.f));
                *(uint32_t*)(g_hh + (size_t)row1 * HIDDEN + col) = *(uint32_t*)&o;
            }
        }
    }
}

// ---------------------------------------------------------------------------
// GEMM2: [q|p] = h @ [Wr2;Wl2]^T  (HMMA fp16 single-pass, 3-stage)
// q -> fp32 g_q, p -> fp16 g_ph.
// ---------------------------------------------------------------------------
#define G2_A   (128 * PITCHB)             // 18432
#define G2_B   (80 * PITCHB)              // 11520
#define G2_STG (G2_A + G2_B)              // 29952
#define G2_SM  (3 * G2_STG)               // 89856

__global__ __launch_bounds__(256, 2)
void gemm2_mma() {
    extern __shared__ char sm[];
    const uint32_t smb = smem_u32(sm);
    const int tid = threadIdx.x;
    const int lane = tid & 31, wid = tid >> 5;
    const int group = lane >> 2, tig = lane & 3;
    const int bm = blockIdx.x * 128;

    float acc[10][4];
#pragma unroll
    for (int nt = 0; nt < 10; nt++)
#pragma unroll
        for (int j = 0; j < 4; j++) acc[nt][j] = 0.f;

    const int aRow = lane & 15;
    const int aColB = (lane >> 4) * 16;
    const int bRow = (lane & 7) + ((lane & 16) ? 8 : 0);
    const int bColB = ((lane >> 3) & 1) * 16;

    auto load_chunk = [&](int kc, int stage) {
        const int koff = kc * 64;
        const uint32_t base = smb + stage * G2_STG;
#pragma unroll
        for (int i = tid; i < 1024; i += 256) {
            int r = i >> 3, c = i & 7;
            int gr = bm + r;
            int sz = (gr < N_NODES) ? 16 : 0;
            int grc = clampi(gr, 0, N_NODES - 1);
            cp16(base + (uint32_t)(r * PITCHB + c * 16),
                 g_hh + (size_t)grc * HIDDEN + koff + c * 8, sz);
        }
#pragma unroll
        for (int i = tid; i < 640; i += 256) {
            int r = i >> 3, c = i & 7;
            cp16(base + G2_A + (uint32_t)(r * PITCHB + c * 16),
                 g_w2 + (size_t)r * 256 + koff + c * 8, 16);
        }
        asm volatile("cp.async.commit_group;" ::: "memory");
    };

    load_chunk(0, 0);
    load_chunk(1, 1);

    for (int kc = 0; kc < 4; kc++) {
        if (kc < 3) {
            asm volatile("cp.async.wait_group 1;" ::: "memory");
        } else {
            asm volatile("cp.async.wait_group 0;" ::: "memory");
        }
        __syncthreads();
        if (kc + 2 < 4) load_chunk(kc + 2, (kc + 2) % 3);

        const uint32_t base = smb + (kc % 3) * G2_STG;
        const uint32_t sA = base, sB = base + G2_A;

#pragma unroll
        for (int k16 = 0; k16 < 4; k16++) {
            const int kbB = k16 * 32;
            uint32_t a[4], bh[10][2];
            {
                uint32_t ad = (uint32_t)((wid * 16 + aRow) * PITCHB + kbB + aColB);
                ldmx4(a, sA + ad);
            }
#pragma unroll
            for (int np = 0; np < 5; np++) {
                uint32_t bd = (uint32_t)((np * 16 + bRow) * PITCHB + kbB + bColB);
                uint32_t th[4];
                ldmx4(th, sB + bd);
                bh[np * 2][0] = th[0]; bh[np * 2][1] = th[1];
                bh[np * 2 + 1][0] = th[2]; bh[np * 2 + 1][1] = th[3];
            }
#pragma unroll
            for (int nt = 0; nt < 10; nt++)
                mma16816(acc[nt], a, bh[nt]);
        }
    }

    // Epilogue: cols 0-39 -> g_q (fp32), cols 40-79 -> g_ph (fp16)
    int row0 = bm + wid * 16 + group;
    int row1 = row0 + 8;
#pragma unroll
    for (int nt = 0; nt < 10; nt++) {
        int col = nt * 8 + tig * 2;
        if (col < 40) {
            if (row0 < N_NODES)
                *(float2*)(g_q + (size_t)row0 * CLASSES + col) =
                    make_float2(acc[nt][0], acc[nt][1]);
            if (row1 < N_NODES)
                *(float2*)(g_q + (size_t)row1 * CLASSES + col) =
                    make_float2(acc[nt][2], acc[nt][3]);
        } else {
            int c = col - 40;
            if (row0 < N_NODES) {
                __half2 o = __floats2half2_rn(acc[nt][0], acc[nt][1]);
                *(uint32_t*)(g_ph + (size_t)row0 * CLASSES + c) = *(uint32_t*)&o;
            }
            if (row1 < N_NODES) {
                __half2 o = __floats2half2_rn(acc[nt][2], acc[nt][3]);
                *(uint32_t*)(g_ph + (size_t)row1 * CLASSES + c) = *(uint32_t*)&o;
            }
        }
    }
}

// ---------------------------------------------------------------------------
// Final fused: out[i] = log_softmax( q[i] + mean_{s in N(i)} p[s] + bl2 )
// ---------------------------------------------------------------------------
__global__ void final_agg_softmax(const float* __restrict__ bl2,
                                  float* __restrict__ out) {
    int w = (blockIdx.x * blockDim.x + threadIdx.x) >> 5;
    int lane = threadIdx.x & 31;
    if (w >= N_NODES) return;

    const bool act = lane < CLASSES / 2;
    int cnt = clampi(g_cnt[w], 0, BKT_CAP);
    const int* bkt = g_bkt + w * BKT_CAP;

    float ax = 0.f, ay = 0.f;
    int i = 0;
    for (; i + 3 < cnt; i += 4) {
        int4 s = *(const int4*)&bkt[i];
        if (act) {
            uint32_t u0 = *(const uint32_t*)&g_ph[s.x * CLASSES + 2 * lane];
            uint32_t u1 = *(const uint32_t*)&g_ph[s.y * CLASSES + 2 * lane];
            uint32_t u2 = *(const uint32_t*)&g_ph[s.z * CLASSES + 2 * lane];
            uint32_t u3 = *(const uint32_t*)&g_ph[s.w * CLASSES + 2 * lane];
            __half2 s01 = __hadd2(*(__half2*)&u0, *(__half2*)&u1);
            __half2 s23 = __hadd2(*(__half2*)&u2, *(__half2*)&u3);
            float2 v = __half22float2(__hadd2(s01, s23));
            ax += v.x; ay += v.y;
        }
    }
    for (; i < cnt; i++) {
        int s0 = bkt[i];
        if (act) {
            uint32_t u0 = *(const uint32_t*)&g_ph[s0 * CLASSES + 2 * lane];
            float2 v = __half22float2(*(__half2*)&u0);
            ax += v.x; ay += v.y;
        }
    }
    float inv = 1.0f / (float)(cnt > 0 ? cnt : 1);

    float vx = -INFINITY, vy = -INFINITY;
    if (act) {
        float2 q = *(const float2*)&g_q[(size_t)w * CLASSES + 2 * lane];
        float2 b = *(const float2*)&bl2[2 * lane];
        vx = q.x + b.x + ax * inv;
        vy = q.y + b.y + ay * inv;
    }

    float mx = fmaxf(vx, vy);
#pragma unroll
    for (int o = 16; o; o >>= 1) mx = fmaxf(mx, __shfl_xor_sync(0xffffffffu, mx, o));
    float s = act ? (expf(vx - mx) + expf(vy - mx)) : 0.f;
#pragma unroll
    for (int o = 16; o; o >>= 1) s += __shfl_xor_sync(0xffffffffu, s, o);
    float l = mx + logf(s);

    if (act) {
        float2 r; r.x = vx - l; r.y = vy - l;
        *(float2*)&out[(size_t)w * CLASSES + 2 * lane] = r;
    }
}

// ---------------------------------------------------------------------------
// Host launcher (graph-capturable: kernel launches only)
// ---------------------------------------------------------------------------
extern "C" void kernel_launch(void* const* d_in, const int* in_sizes, int n_in,
                              void* d_out, int out_size) {
    const float* x   = (const float*)d_in[0];
    const int*   ei  = (const int*)d_in[1];      // int32 (JAX x64 disabled)
    const float* Wl1 = (const float*)d_in[2];
    const float* bl1 = (const float*)d_in[3];
    const float* Wr1 = (const float*)d_in[4];
    const float* Wl2 = (const float*)d_in[5];
    const float* bl2 = (const float*)d_in[6];
    const float* Wr2 = (const float*)d_in[7];
    float*       out = (float*)d_out;

    const int E = in_sizes[1] / 2;
    const int* src = ei;
    const int* dst = ei + E;

    cudaFuncSetAttribute(gemm1_mma, cudaFuncAttributeMaxDynamicSharedMemorySize, G1_SM);
    cudaFuncSetAttribute(gemm2_mma, cudaFuncAttributeMaxDynamicSharedMemorySize, G2_SM);

    // 1. fused conversion (x, W1, W2) + zero counters
    cvt_all<<<(N_NODES * D_FEAT / 4 + 255) / 256, 256>>>(x, Wr1, Wl1, Wr2, Wl2);

    // 2. bucket fill (CSR replacement), 4 edges per thread
    fill_bkt<<<(E / 4 + 256) / 256, 256>>>(src, dst, E);

    // 3. aggregate x (fp16 source), half-warp per node, 8-deep pipeline
    agg_gather_x<<<(N_NODES * 16 + 255) / 256, 256>>>();

    // 4. layer 1 (HMMA fp16, BM=128 BN=128, 3-stage pipeline)
    {
        dim3 grid((N_NODES + 127) / 128, HIDDEN / 128);
        gemm1_mma<<<grid, 256, G1_SM>>>(bl1);
    }

    // 5. layer 2 projections (merged q|p, 3-stage pipeline)
    gemm2_mma<<<(N_NODES + 127) / 128, 256, G2_SM>>>();

    // 6. fused mean-aggregate(p fp16) + q + bias + log_softmax
    final_agg_softmax<<<(N_NODES * 32 + 255) / 256, 256>>>(bl2, out);
}